// round 1
// baseline (speedup 1.0000x reference)
#include <cuda_runtime.h>

// CausalConv1d: x (4, 2048, 8192) f32, depthwise weight (2048, 1, 16), bias (2048)
// out[n,c,l] = sum_{k=0..15} x[n,c,l-15+k] * w[c,0,k] + bias[c]   (x zero-padded left)

#define DIM   2048
#define LEN   8192
#define KSZ   16
#define TILE  1024
#define BLOCK 256
#define OPT   4            // outputs per thread = TILE/BLOCK
#define TILES_PER_ROW (LEN / TILE)   // 8

__global__ __launch_bounds__(BLOCK) void causal_conv1d_kernel(
    const float* __restrict__ x,
    const float* __restrict__ w,
    const float* __restrict__ bias,
    float* __restrict__ out)
{
    // smem tile: s[i] = xrow[in0 + i], i in [0, TILE+16)
    __shared__ float s[TILE + 16];
    __shared__ float sw[KSZ];

    const int tid  = threadIdx.x;
    const int row  = blockIdx.x >> 3;          // / TILES_PER_ROW
    const int tile = blockIdx.x & (TILES_PER_ROW - 1);
    const int ch   = row & (DIM - 1);          // row = n*DIM + c

    const float* xrow = x   + (size_t)row * LEN;
    float*       orow = out + (size_t)row * LEN;

    const int in0 = tile * TILE - 16;          // aligned to 16 floats

    // ---- stage inputs: (TILE+16)/4 = 260 float4 loads, aligned, coalesced ----
    #pragma unroll
    for (int v = tid; v < (TILE + 16) / 4; v += BLOCK) {
        const int g = in0 + 4 * v;             // whole-vector granularity: fully <0 or fully valid
        float4 val = make_float4(0.f, 0.f, 0.f, 0.f);
        if (g >= 0) val = *reinterpret_cast<const float4*>(xrow + g);
        *reinterpret_cast<float4*>(s + 4 * v) = val;
    }
    if (tid < KSZ) sw[tid] = w[ch * KSZ + tid];
    __syncthreads();

    // ---- weights + bias into registers (broadcast reads) ----
    float wr[KSZ];
    #pragma unroll
    for (int k = 0; k < KSZ; k++) wr[k] = sw[k];
    const float b = bias[ch];

    // ---- sliding window: r[0..19] = s[4*tid .. 4*tid+19], 5x LDS.128 conflict-free ----
    float r[OPT + KSZ];                        // 20
    const float4* s4 = reinterpret_cast<const float4*>(s);
    #pragma unroll
    for (int q = 0; q < 5; q++) {
        float4 v = s4[tid + q];
        r[4 * q + 0] = v.x; r[4 * q + 1] = v.y; r[4 * q + 2] = v.z; r[4 * q + 3] = v.w;
    }

    // out local index j = 4*tid + m needs s[j+1+k] = r[m+1+k]
    float4 o;
    float acc[OPT];
    #pragma unroll
    for (int m = 0; m < OPT; m++) {
        float a = b;
        #pragma unroll
        for (int k = 0; k < KSZ; k++) a = fmaf(wr[k], r[m + 1 + k], a);
        acc[m] = a;
    }
    o.x = acc[0]; o.y = acc[1]; o.z = acc[2]; o.w = acc[3];

    *reinterpret_cast<float4*>(orow + tile * TILE + 4 * tid) = o;
}

extern "C" void kernel_launch(void* const* d_in, const int* in_sizes, int n_in,
                              void* d_out, int out_size)
{
    const float* x    = (const float*)d_in[0];
    const float* w    = (const float*)d_in[1];
    const float* bias = (const float*)d_in[2];
    float* out        = (float*)d_out;

    const int rows = 4 * DIM;                      // 8192
    const int blocks = rows * TILES_PER_ROW;       // 65536
    causal_conv1d_kernel<<<blocks, BLOCK>>>(x, w, bias, out);
}

// round 2
// speedup vs baseline: 1.1558x; 1.1558x over previous
#include <cuda_runtime.h>

// CausalConv1d: x (4, 2048, 8192) f32, depthwise weight (2048, 1, 16), bias (2048)
// out[n,c,l] = sum_{k=0..15} x[n,c,l-15+k] * w[c,0,k] + bias[c]   (zero-pad left)
//
// No shared memory: each thread computes 4 consecutive outputs and fetches its
// 20-float window with 5 overlapping, warp-coalesced LDG.128 (offsets -16..0
// floats from its output base). Overlap hits L1; DRAM traffic stays ~in+out.

#define DIM   2048
#define LEN   8192
#define KSZ   16
#define TILE  1024
#define BLOCK 256
#define OPT   4
#define TILES_PER_ROW (LEN / TILE)   // 8

__global__ __launch_bounds__(BLOCK) void causal_conv1d_kernel(
    const float* __restrict__ x,
    const float* __restrict__ w,
    const float* __restrict__ bias,
    float* __restrict__ out)
{
    const int tid  = threadIdx.x;
    const int row  = blockIdx.x >> 3;           // / TILES_PER_ROW
    const int tile = blockIdx.x & (TILES_PER_ROW - 1);
    const int ch   = row & (DIM - 1);           // row = n*DIM + c

    const float* __restrict__ xrow = x   + (size_t)row * LEN;
    float*       __restrict__ orow = out + (size_t)row * LEN;

    const int base = tile * TILE + OPT * tid;   // first output index in row (mult of 4)

    // ---- fetch 20-float window r[i] = xrow[base - 16 + i], i in [0,20) ----
    // 5 vec4 loads, each coalesced across the warp; left edge zero-padded
    // (window indices are multiples of 4, so vectors never straddle 0).
    float r[OPT + KSZ];
    #pragma unroll
    for (int j = 0; j < 5; j++) {
        const int m = base - 16 + 4 * j;
        float4 v = make_float4(0.f, 0.f, 0.f, 0.f);
        if (m >= 0) v = *reinterpret_cast<const float4*>(xrow + m);
        r[4 * j + 0] = v.x; r[4 * j + 1] = v.y;
        r[4 * j + 2] = v.z; r[4 * j + 3] = v.w;
    }

    // ---- weights: 4 uniform vec4 loads (L1 broadcast), bias scalar ----
    float wr[KSZ];
    const float4* w4 = reinterpret_cast<const float4*>(w + ch * KSZ);
    #pragma unroll
    for (int q = 0; q < 4; q++) {
        float4 v = w4[q];
        wr[4 * q + 0] = v.x; wr[4 * q + 1] = v.y;
        wr[4 * q + 2] = v.z; wr[4 * q + 3] = v.w;
    }
    const float b = bias[ch];

    // ---- compute: out[base+m] = b + sum_k wr[k] * r[m+1+k] ----
    float acc[OPT];
    #pragma unroll
    for (int m = 0; m < OPT; m++) {
        float a = b;
        #pragma unroll
        for (int k = 0; k < KSZ; k++) a = fmaf(wr[k], r[m + 1 + k], a);
        acc[m] = a;
    }

    float4 o; o.x = acc[0]; o.y = acc[1]; o.z = acc[2]; o.w = acc[3];
    *reinterpret_cast<float4*>(orow + base) = o;
}

extern "C" void kernel_launch(void* const* d_in, const int* in_sizes, int n_in,
                              void* d_out, int out_size)
{
    const float* x    = (const float*)d_in[0];
    const float* w    = (const float*)d_in[1];
    const float* bias = (const float*)d_in[2];
    float* out        = (float*)d_out;

    const int rows = 4 * DIM;                    // 8192
    const int blocks = rows * TILES_PER_ROW;     // 65536
    causal_conv1d_kernel<<<blocks, BLOCK>>>(x, w, bias, out);
}